// round 2
// baseline (speedup 1.0000x reference)
#include <cuda_runtime.h>
#include <cuda_fp16.h>
#include <cstdint>

#define NB 8
#define HGT 60
#define WID 80
#define PP (NB*HGT*WID)   // 38400 positions

// ---------------- static scratch ----------------
__device__ __half g_x1[(size_t)PP*512];
__device__ __half g_ya[(size_t)PP*256];
__device__ __half g_yb[(size_t)PP*256];
__device__ float  g_gx[(size_t)PP*1024];
__device__ __half g_bmat[(size_t)1280*1024];   // Wih^T fp16 (layer row-offsets 0/512K/768K/1024K)
__device__ __half g_wrec[(size_t)4*2*512*128]; // Whh fp16
__device__ float  g_scp[4*8*1024];             // scene-context projections per layer
__device__ float  g_sc1[8*512];
__device__ float  g_scr[8*256];
__device__ float  g_score[PP];

// ---------------- helpers ----------------
__device__ __forceinline__ float sigm(float x){ return __fdividef(1.f, 1.f + __expf(-x)); }
__device__ __forceinline__ float tanh_(float x){ float e = __expf(2.f*x); return 1.f - __fdividef(2.f, e + 1.f); }

__device__ __forceinline__ void ldsm4(uint32_t* r, const void* p){
  uint32_t a = (uint32_t)__cvta_generic_to_shared(p);
  asm volatile("ldmatrix.sync.aligned.m8n8.x4.shared.b16 {%0,%1,%2,%3}, [%4];\n"
    : "=r"(r[0]),"=r"(r[1]),"=r"(r[2]),"=r"(r[3]) : "r"(a));
}
__device__ __forceinline__ void ldsm4t(uint32_t* r, const void* p){
  uint32_t a = (uint32_t)__cvta_generic_to_shared(p);
  asm volatile("ldmatrix.sync.aligned.m8n8.x4.trans.shared.b16 {%0,%1,%2,%3}, [%4];\n"
    : "=r"(r[0]),"=r"(r[1]),"=r"(r[2]),"=r"(r[3]) : "r"(a));
}
__device__ __forceinline__ void mma16816(float* c, const uint32_t* a, uint32_t b0, uint32_t b1){
  asm volatile(
    "mma.sync.aligned.m16n8k16.row.col.f32.f16.f16.f32 "
    "{%0,%1,%2,%3}, {%4,%5,%6,%7}, {%8,%9}, {%0,%1,%2,%3};\n"
    : "+f"(c[0]), "+f"(c[1]), "+f"(c[2]), "+f"(c[3])
    : "r"(a[0]), "r"(a[1]), "r"(a[2]), "r"(a[3]), "r"(b0), "r"(b1));
}
__device__ __forceinline__ const __half* pick_x(int s){
  return s==0 ? g_x1 : (s==1 ? g_ya : g_yb);
}
__device__ __forceinline__ __half* pick_y(int s){
  return s==1 ? g_ya : g_yb;
}

// ---------------- prep kernels ----------------
__global__ void k_scene_fc(const float* __restrict__ scene,
                           const float* __restrict__ fc1w, const float* __restrict__ fc1b,
                           const float* __restrict__ fcrw, const float* __restrict__ fcrb){
  __shared__ float s[128];
  int n = blockIdx.x, t = threadIdx.x;
  if (t < 128) s[t] = scene[n*128 + t];
  __syncthreads();
  if (t < 512){
    float a = fc1b[t];
    #pragma unroll 8
    for (int k=0;k<128;k++) a += s[k]*fc1w[t*128+k];
    g_sc1[n*512 + t] = a;
  } else {
    int o = t - 512;
    float a = fcrb[o];
    #pragma unroll 8
    for (int k=0;k<128;k++) a += s[k]*fcrw[o*128+k];
    g_scr[n*256 + o] = a;
  }
}

__global__ void k_conv_wih(const float* __restrict__ wih, int I, int bmoff){
  int id = blockIdx.x*blockDim.x + threadIdx.x;
  if (id >= I*1024) return;
  int k = id >> 10, col = id & 1023;
  g_bmat[(size_t)bmoff + id] = __float2half(wih[(size_t)col*I + k]);
}

__global__ void k_cast_whh(const float* __restrict__ whh, int off){
  int id = blockIdx.x*blockDim.x + threadIdx.x;
  if (id < 2*512*128) g_wrec[off + id] = __float2half(whh[id]);
}

__global__ void k_scproj(const float* __restrict__ wih, int I, int use_sc1, int outoff){
  __shared__ float s[512];
  int n = blockIdx.x, t = threadIdx.x;
  const float* sc = use_sc1 ? (g_sc1 + n*512) : (g_scr + n*256);
  if (t < I) s[t] = sc[t];
  __syncthreads();
  float a = 0.f;
  const float* wp = wih + (size_t)t * I;
  for (int k=0;k<I;k++) a += s[k]*wp[k];
  g_scp[outoff + n*1024 + t] = a;
}

// local_feats [n][c][4800] fp32 -> g_x1 [n*4800][512] fp16
__global__ void k_build_x1(const float* __restrict__ lf){
  __shared__ float tile[32][33];
  int p0 = blockIdx.x*32, c0 = blockIdx.y*32, n = blockIdx.z;
  int tx = threadIdx.x, ty = threadIdx.y;
  #pragma unroll
  for (int i=0;i<4;i++)
    tile[ty + i*8][tx] = lf[((size_t)(n*512 + c0 + ty + i*8))*4800 + p0 + tx];
  __syncthreads();
  #pragma unroll
  for (int i=0;i<4;i++)
    g_x1[((size_t)(n*4800 + p0 + ty + i*8))*512 + c0 + tx] = __float2half(tile[tx][ty + i*8]);
}

// ---------------- input-projection GEMM (tensor cores) ----------------
__global__ __launch_bounds__(256) void k_gemm_proj(
    int xsel, int bmoff, const float* __restrict__ bias, int scpoff,
    int I, int scan_type){
  __shared__ __half As[128][72];
  __shared__ __half Bs[64][136];
  const __half* __restrict__ X = pick_x(xsel);
  const __half* __restrict__ Bm = g_bmat + (size_t)bmoff;
  const int tid = threadIdx.x, lane = tid & 31, wp = tid >> 5;
  const int wm = wp & 3, wn = wp >> 2;
  const int m0 = blockIdx.x * 128, n0 = blockIdx.y * 128;
  float acc[2][8][4];
  #pragma unroll
  for (int a=0;a<2;a++)
    #pragma unroll
    for (int b=0;b<8;b++)
      #pragma unroll
      for (int c=0;c<4;c++) acc[a][b][c]=0.f;

  for (int k0 = 0; k0 < I; k0 += 64){
    #pragma unroll
    for (int i=0;i<4;i++){
      int idx = tid + i*256;
      int r = idx >> 3, cb = (idx & 7) * 8;
      *(uint4*)&As[r][cb] = *(const uint4*)&X[(size_t)(m0 + r) * I + k0 + cb];
    }
    #pragma unroll
    for (int i=0;i<4;i++){
      int idx = tid + i*256;
      int r = idx >> 4, cb = (idx & 15) * 8;
      *(uint4*)&Bs[r][cb] = *(const uint4*)&Bm[(size_t)(k0 + r) * 1024 + n0 + cb];
    }
    __syncthreads();
    #pragma unroll
    for (int kc=0;kc<4;kc++){
      uint32_t a[2][4];
      #pragma unroll
      for (int mt=0;mt<2;mt++){
        int row = wm*32 + mt*16 + ((lane>>3)&1)*8 + (lane&7);
        int col = kc*16 + (lane>>4)*8;
        ldsm4(a[mt], &As[row][col]);
      }
      #pragma unroll
      for (int p=0;p<4;p++){
        uint32_t b[4];
        int row = kc*16 + ((lane>>3)&1)*8 + (lane&7);
        int col = wn*64 + p*16 + (lane>>4)*8;
        ldsm4t(b, &Bs[row][col]);
        #pragma unroll
        for (int mt=0;mt<2;mt++){
          mma16816(acc[mt][2*p],   a[mt], b[0], b[1]);
          mma16816(acc[mt][2*p+1], a[mt], b[2], b[3]);
        }
      }
    }
    __syncthreads();
  }
  const int r0 = lane >> 2, cc0 = (lane & 3) * 2;
  const float* scp = g_scp + scpoff;
  #pragma unroll
  for (int mt=0; mt<2; mt++)
    #pragma unroll
    for (int hf=0; hf<2; hf++){
      int m = m0 + wm*32 + mt*16 + hf*8 + r0;
      bool bnd;
      if (scan_type==0){ int wv = m % 80; bnd = (wv==0)||(wv==79); }
      else { int hv = (m/80)%60; bnd = (hv==0)||(hv==59); }
      const float* sp = scp + (m/4800)*1024;
      #pragma unroll
      for (int nt=0;nt<8;nt++){
        int c = n0 + wn*64 + nt*8 + cc0;
        float v0 = acc[mt][nt][hf*2+0] + bias[c];
        float v1 = acc[mt][nt][hf*2+1] + bias[c+1];
        if (bnd){ v0 += sp[c]; v1 += sp[c+1]; }
        float2 vv; vv.x = v0; vv.y = v1;
        *(float2*)&g_gx[(size_t)m*1024 + c] = vv;
      }
    }
}

// ---------------- persistent BLSTM scan ----------------
__global__ __launch_bounds__(256) void k_scan(
    int layer, int ysel, int scan_type, int T, int bpd){
  __shared__ __half hsm[16][136];
  __shared__ float gsm[16][528];
  __half* __restrict__ yout = pick_y(ysel);
  const int tid = threadIdx.x, lane = tid & 31, wp = tid >> 5;
  const int dir = blockIdx.x / bpd;
  const int s0 = (blockIdx.x % bpd) * 16;
  const __half* __restrict__ wd = g_wrec + (size_t)layer*131072 + (size_t)dir*65536;
  const int nbase = wp * 64;

  // recurrent-weight mma B fragments (held in registers)
  uint32_t bf[8][8][2];
  #pragma unroll
  for (int kc=0;kc<8;kc++)
    #pragma unroll
    for (int nt=0;nt<8;nt++){
      int n = nbase + nt*8 + (lane>>2);
      int k = kc*16 + (lane&3)*2;
      bf[kc][nt][0] = *(const uint32_t*)&wd[(size_t)n*128 + k];
      bf[kc][nt][1] = *(const uint32_t*)&wd[(size_t)n*128 + k + 8];
    }

  for (int i = tid; i < 16*136; i += 256) ((__half*)hsm)[i] = __ushort_as_half((unsigned short)0);

  // pointwise mapping: thread owns seq sL, hidden units j = u*16 + jl
  const int sL = tid >> 4, jl = tid & 15;
  size_t posbase; int pstride;
  {
    int s = s0 + sL;
    if (scan_type == 0){ posbase = (size_t)s * 80; pstride = 1; }
    else { posbase = (size_t)(s/80)*4800 + (s%80); pstride = 80; }
  }
  float cst[8];
  #pragma unroll
  for (int u=0;u<8;u++) cst[u]=0.f;
  __syncthreads();

  for (int t=0; t<T; ++t){
    size_t pos = posbase + (size_t)(dir ? (T-1-t) : t) * pstride;
    const float* gp = g_gx + pos*1024 + dir*512;
    // prefetch gx for this step (in flight during mma)
    float gxr[32];
    #pragma unroll
    for (int g4=0; g4<4; ++g4)
      #pragma unroll
      for (int u=0;u<8;++u)
        gxr[g4*8+u] = gp[g4*128 + u*16 + jl];

    // gates = h @ Whh^T
    float acc[8][4];
    #pragma unroll
    for (int nt=0;nt<8;nt++)
      #pragma unroll
      for (int q=0;q<4;q++) acc[nt][q]=0.f;
    #pragma unroll
    for (int kc=0;kc<8;kc++){
      uint32_t a[4];
      ldsm4(a, &hsm[lane & 15][kc*16 + (lane>>4)*8]);
      #pragma unroll
      for (int nt=0;nt<8;nt++)
        mma16816(acc[nt], a, bf[kc][nt][0], bf[kc][nt][1]);
    }
    {
      int r = lane >> 2, cb = (lane & 3) * 2;
      #pragma unroll
      for (int nt=0;nt<8;nt++){
        int col = nbase + nt*8 + cb;
        float2 v0; v0.x = acc[nt][0]; v0.y = acc[nt][1];
        float2 v1; v1.x = acc[nt][2]; v1.y = acc[nt][3];
        *(float2*)&gsm[r][col]   = v0;
        *(float2*)&gsm[r+8][col] = v1;
      }
    }
    __syncthreads();
    // pointwise cell update
    #pragma unroll
    for (int u=0;u<8;u++){
      int j = u*16 + jl;
      float gi = gsm[sL][j]       + gxr[0*8+u];
      float gf = gsm[sL][128 + j] + gxr[1*8+u];
      float gg = gsm[sL][256 + j] + gxr[2*8+u];
      float go = gsm[sL][384 + j] + gxr[3*8+u];
      float c = sigm(gf)*cst[u] + sigm(gi)*tanh_(gg);
      cst[u] = c;
      float h = sigm(go)*tanh_(c);
      hsm[sL][j] = __float2half(h);
      yout[pos*256 + dir*128 + j] = __float2half(h);
    }
    __syncthreads();
  }
}

// ---------------- output head ----------------
__global__ void k_conv_sig(int ysel, const float* __restrict__ cw, const float* __restrict__ cb){
  __shared__ float w[256];
  int tid = threadIdx.x;
  w[tid] = cw[tid];
  __syncthreads();
  int pos = blockIdx.x*256 + tid;
  const __half* yp = pick_x(ysel) + (size_t)pos*256;
  float a = cb[0];
  #pragma unroll 8
  for (int c=0;c<256;c++) a += __half2float(yp[c])*w[c];
  g_score[pos] = sigm(a);
}

__global__ void k_upsample(float* __restrict__ out){
  int idx = blockIdx.x*blockDim.x + threadIdx.x;
  if (idx >= NB*480*640) return;
  int ox = idx % 640, oy = (idx/640) % 480, n = idx/(640*480);
  float sy = oy * (59.f/479.f);
  int iy = (int)sy; if (iy > 58) iy = 58;
  float ty = sy - (float)iy;
  float sx = ox * (79.f/639.f);
  int ix = (int)sx; if (ix > 78) ix = 78;
  float tx = sx - (float)ix;
  const float* sp = g_score + n*4800;
  float v00 = sp[iy*80+ix],     v01 = sp[iy*80+ix+1];
  float v10 = sp[(iy+1)*80+ix], v11 = sp[(iy+1)*80+ix+1];
  out[idx] = (v00*(1.f-ty)+v10*ty)*(1.f-tx) + (v01*(1.f-ty)+v11*ty)*tx;
}

// ---------------- launch ----------------
extern "C" void kernel_launch(void* const* d_in, const int* in_sizes, int n_in,
                              void* d_out, int out_size){
  const float* lf   = (const float*)d_in[0];
  const float* sc   = (const float*)d_in[1];
  const float* fc1w = (const float*)d_in[2];
  const float* fc1b = (const float*)d_in[3];
  const float* fcrw = (const float*)d_in[4];
  const float* fcrb = (const float*)d_in[5];
  const float* wih[4] = {(const float*)d_in[6], (const float*)d_in[9],
                         (const float*)d_in[12], (const float*)d_in[15]};
  const float* whh[4] = {(const float*)d_in[7], (const float*)d_in[10],
                         (const float*)d_in[13], (const float*)d_in[16]};
  const float* bb[4]  = {(const float*)d_in[8], (const float*)d_in[11],
                         (const float*)d_in[14], (const float*)d_in[17]};
  const float* cw = (const float*)d_in[18];
  const float* cb = (const float*)d_in[19];
  float* out = (float*)d_out;

  int bmoff[4] = {0, 512*1024, 768*1024, 1024*1024};
  int Is[4]    = {512, 256, 256, 256};

  k_scene_fc<<<8, 768>>>(sc, fc1w, fc1b, fcrw, fcrb);
  for (int L=0; L<4; L++){
    k_conv_wih<<<(Is[L]*1024 + 255)/256, 256>>>(wih[L], Is[L], bmoff[L]);
    k_cast_whh<<<512, 256>>>(whh[L], L*131072);
    k_scproj<<<8, 1024>>>(wih[L], Is[L], (L==0)?1:0, L*8192);
  }
  k_build_x1<<<dim3(150,16,8), dim3(32,8)>>>(lf);

  // layer 1: rows (T=80, 480 seqs)
  k_gemm_proj<<<dim3(300,8), 256>>>(0, bmoff[0], bb[0], 0,     512, 0);
  k_scan<<<60, 256>>>(0, 1, 0, 80, 30);
  // layer 2: cols (T=60, 640 seqs)
  k_gemm_proj<<<dim3(300,8), 256>>>(1, bmoff[1], bb[1], 8192,  256, 1);
  k_scan<<<80, 256>>>(1, 2, 1, 60, 40);
  // layer 3: rows
  k_gemm_proj<<<dim3(300,8), 256>>>(2, bmoff[2], bb[2], 16384, 256, 0);
  k_scan<<<60, 256>>>(2, 1, 0, 80, 30);
  // layer 4: cols
  k_gemm_proj<<<dim3(300,8), 256>>>(1, bmoff[3], bb[3], 24576, 256, 1);
  k_scan<<<80, 256>>>(3, 2, 1, 60, 40);

  k_conv_sig<<<150, 256>>>(2, cw, cb);
  k_upsample<<<(NB*480*640 + 255)/256, 256>>>(out);
}

// round 4
// speedup vs baseline: 1.4629x; 1.4629x over previous
#include <cuda_runtime.h>
#include <cuda_fp16.h>
#include <cstdint>

#define NB 8
#define HGT 60
#define WID 80
#define PP (NB*HGT*WID)   // 38400 positions

// ---------------- static scratch ----------------
__device__ __half g_x1[(size_t)PP*512];
__device__ __half g_ya[(size_t)PP*256];
__device__ __half g_yb[(size_t)PP*256];
__device__ float  g_gx[(size_t)PP*1024];
__device__ __half g_bmat[(size_t)1280*1024];   // Wih^T fp16 (layer row-offsets 0/512K/768K/1024K)
__device__ __half g_wrec[(size_t)4*2*512*128]; // Whh fp16
__device__ float  g_scp[4*8*1024];             // scene-context projections per layer
__device__ float  g_sc1[8*512];
__device__ float  g_scr[8*256];
__device__ float  g_score[PP];

// ---------------- helpers ----------------
__device__ __forceinline__ float sigm(float x){ return __fdividef(1.f, 1.f + __expf(-x)); }
__device__ __forceinline__ float tanh_(float x){ float e = __expf(2.f*x); return 1.f - __fdividef(2.f, e + 1.f); }

__device__ __forceinline__ void ldsm4(uint32_t* r, const void* p){
  uint32_t a = (uint32_t)__cvta_generic_to_shared(p);
  asm volatile("ldmatrix.sync.aligned.m8n8.x4.shared.b16 {%0,%1,%2,%3}, [%4];\n"
    : "=r"(r[0]),"=r"(r[1]),"=r"(r[2]),"=r"(r[3]) : "r"(a));
}
__device__ __forceinline__ void ldsm4t(uint32_t* r, const void* p){
  uint32_t a = (uint32_t)__cvta_generic_to_shared(p);
  asm volatile("ldmatrix.sync.aligned.m8n8.x4.trans.shared.b16 {%0,%1,%2,%3}, [%4];\n"
    : "=r"(r[0]),"=r"(r[1]),"=r"(r[2]),"=r"(r[3]) : "r"(a));
}
__device__ __forceinline__ void mma16816(float* c, const uint32_t* a, uint32_t b0, uint32_t b1){
  asm volatile(
    "mma.sync.aligned.m16n8k16.row.col.f32.f16.f16.f32 "
    "{%0,%1,%2,%3}, {%4,%5,%6,%7}, {%8,%9}, {%0,%1,%2,%3};\n"
    : "+f"(c[0]), "+f"(c[1]), "+f"(c[2]), "+f"(c[3])
    : "r"(a[0]), "r"(a[1]), "r"(a[2]), "r"(a[3]), "r"(b0), "r"(b1));
}
__device__ __forceinline__ const __half* pick_x(int s){
  return s==0 ? g_x1 : (s==1 ? g_ya : g_yb);
}
__device__ __forceinline__ __half* pick_y(int s){
  return s==1 ? g_ya : g_yb;
}

// ---------------- prep kernels (coalesced) ----------------

// warp-per-output scene fc; outputs 0..511 -> sc1, 512..767 -> scr
// FIX: full 128-wide dot product = 4 terms per lane (was 2).
__global__ __launch_bounds__(256) void k_scene_fc(
    const float* __restrict__ scene,
    const float* __restrict__ fc1w, const float* __restrict__ fc1b,
    const float* __restrict__ fcrw, const float* __restrict__ fcrb){
  __shared__ float s[8][128];
  int tid = threadIdx.x, lane = tid & 31, wp = tid >> 5;
  for (int i = tid; i < 1024; i += 256) s[i>>7][i&127] = scene[i];
  __syncthreads();
  int o = blockIdx.x*8 + wp;
  const float* wrow; float b; float* outp; int stride;
  if (o < 512){ wrow = fc1w + o*128; b = fc1b[o]; outp = g_sc1 + o; stride = 512; }
  else { int oo = o-512; wrow = fcrw + oo*128; b = fcrb[oo]; outp = g_scr + oo; stride = 256; }
  float w0 = wrow[lane], w1 = wrow[32+lane], w2 = wrow[64+lane], w3 = wrow[96+lane];
  #pragma unroll
  for (int n=0;n<8;n++){
    float p = w0*s[n][lane] + w1*s[n][32+lane] + w2*s[n][64+lane] + w3*s[n][96+lane];
    #pragma unroll
    for (int d=16;d;d>>=1) p += __shfl_xor_sync(0xffffffffu, p, d);
    if (lane == 0) outp[n*stride] = p + b;
  }
}

// tiled transpose: g_bmat[k][col] = wih[col][k]
__global__ __launch_bounds__(256) void k_conv_wih(const float* __restrict__ wih, int I, int bmoff){
  __shared__ float tile[32][33];
  int k0 = blockIdx.x*32, c0 = blockIdx.y*32;
  int tx = threadIdx.x, ty = threadIdx.y;
  #pragma unroll
  for (int i=0;i<4;i++)
    tile[ty + i*8][tx] = wih[(size_t)(c0 + ty + i*8)*I + k0 + tx];
  __syncthreads();
  #pragma unroll
  for (int i=0;i<4;i++)
    g_bmat[(size_t)bmoff + (size_t)(k0 + ty + i*8)*1024 + c0 + tx] = __float2half(tile[tx][ty + i*8]);
}

__global__ void k_cast_whh(const float* __restrict__ whh, int off){
  int id = blockIdx.x*blockDim.x + threadIdx.x;
  if (id < 2*512*128) g_wrec[off + id] = __float2half(whh[id]);
}

// scp[n][col] = sum_k sc[n][k] * bmat[k][col]   (coalesced fp16 reads)
__global__ __launch_bounds__(256) void k_scproj(int bmoff, int I, int use_sc1, int outoff){
  __shared__ float s[8*512];
  int tid = threadIdx.x;
  int col = blockIdx.x*256 + tid;
  for (int i = tid; i < 8*I; i += 256){
    int n = i / I, k = i - n*I;
    s[i] = use_sc1 ? g_sc1[n*512 + k] : g_scr[n*256 + k];
  }
  __syncthreads();
  float acc[8];
  #pragma unroll
  for (int n=0;n<8;n++) acc[n] = 0.f;
  const __half* bp = g_bmat + (size_t)bmoff + col;
  #pragma unroll 4
  for (int k=0;k<I;k++){
    float w = __half2float(bp[(size_t)k*1024]);
    #pragma unroll
    for (int n=0;n<8;n++) acc[n] += s[n*I + k] * w;
  }
  #pragma unroll
  for (int n=0;n<8;n++) g_scp[outoff + n*1024 + col] = acc[n];
}

// local_feats [n][c][4800] fp32 -> g_x1 [n*4800][512] fp16
__global__ void k_build_x1(const float* __restrict__ lf){
  __shared__ float tile[32][33];
  int p0 = blockIdx.x*32, c0 = blockIdx.y*32, n = blockIdx.z;
  int tx = threadIdx.x, ty = threadIdx.y;
  #pragma unroll
  for (int i=0;i<4;i++)
    tile[ty + i*8][tx] = lf[((size_t)(n*512 + c0 + ty + i*8))*4800 + p0 + tx];
  __syncthreads();
  #pragma unroll
  for (int i=0;i<4;i++)
    g_x1[((size_t)(n*4800 + p0 + ty + i*8))*512 + c0 + tx] = __float2half(tile[tx][ty + i*8]);
}

// ---------------- input-projection GEMM (tensor cores) ----------------
__global__ __launch_bounds__(256) void k_gemm_proj(
    int xsel, int bmoff, const float* __restrict__ bias, int scpoff,
    int I, int scan_type){
  __shared__ __half As[128][72];
  __shared__ __half Bs[64][136];
  const __half* __restrict__ X = pick_x(xsel);
  const __half* __restrict__ Bm = g_bmat + (size_t)bmoff;
  const int tid = threadIdx.x, lane = tid & 31, wp = tid >> 5;
  const int wm = wp & 3, wn = wp >> 2;
  const int m0 = blockIdx.x * 128, n0 = blockIdx.y * 128;
  float acc[2][8][4];
  #pragma unroll
  for (int a=0;a<2;a++)
    #pragma unroll
    for (int b=0;b<8;b++)
      #pragma unroll
      for (int c=0;c<4;c++) acc[a][b][c]=0.f;

  for (int k0 = 0; k0 < I; k0 += 64){
    #pragma unroll
    for (int i=0;i<4;i++){
      int idx = tid + i*256;
      int r = idx >> 3, cb = (idx & 7) * 8;
      *(uint4*)&As[r][cb] = *(const uint4*)&X[(size_t)(m0 + r) * I + k0 + cb];
    }
    #pragma unroll
    for (int i=0;i<4;i++){
      int idx = tid + i*256;
      int r = idx >> 4, cb = (idx & 15) * 8;
      *(uint4*)&Bs[r][cb] = *(const uint4*)&Bm[(size_t)(k0 + r) * 1024 + n0 + cb];
    }
    __syncthreads();
    #pragma unroll
    for (int kc=0;kc<4;kc++){
      uint32_t a[2][4];
      #pragma unroll
      for (int mt=0;mt<2;mt++){
        int row = wm*32 + mt*16 + ((lane>>3)&1)*8 + (lane&7);
        int col = kc*16 + (lane>>4)*8;
        ldsm4(a[mt], &As[row][col]);
      }
      #pragma unroll
      for (int p=0;p<4;p++){
        uint32_t b[4];
        int row = kc*16 + ((lane>>3)&1)*8 + (lane&7);
        int col = wn*64 + p*16 + (lane>>4)*8;
        ldsm4t(b, &Bs[row][col]);
        #pragma unroll
        for (int mt=0;mt<2;mt++){
          mma16816(acc[mt][2*p],   a[mt], b[0], b[1]);
          mma16816(acc[mt][2*p+1], a[mt], b[2], b[3]);
        }
      }
    }
    __syncthreads();
  }
  const int r0 = lane >> 2, cc0 = (lane & 3) * 2;
  const float* scp = g_scp + scpoff;
  #pragma unroll
  for (int mt=0; mt<2; mt++)
    #pragma unroll
    for (int hf=0; hf<2; hf++){
      int m = m0 + wm*32 + mt*16 + hf*8 + r0;
      bool bnd;
      if (scan_type==0){ int wv = m % 80; bnd = (wv==0)||(wv==79); }
      else { int hv = (m/80)%60; bnd = (hv==0)||(hv==59); }
      const float* sp = scp + (m/4800)*1024;
      #pragma unroll
      for (int nt=0;nt<8;nt++){
        int c = n0 + wn*64 + nt*8 + cc0;
        float v0 = acc[mt][nt][hf*2+0] + bias[c];
        float v1 = acc[mt][nt][hf*2+1] + bias[c+1];
        if (bnd){ v0 += sp[c]; v1 += sp[c+1]; }
        float2 vv; vv.x = v0; vv.y = v1;
        *(float2*)&g_gx[(size_t)m*1024 + c] = vv;
      }
    }
}

// ---------------- persistent BLSTM scan ----------------
__global__ __launch_bounds__(256) void k_scan(
    int layer, int ysel, int scan_type, int T, int bpd){
  __shared__ __half hsm[16][136];
  __shared__ float gsm[16][528];
  __half* __restrict__ yout = pick_y(ysel);
  const int tid = threadIdx.x, lane = tid & 31, wp = tid >> 5;
  const int dir = blockIdx.x / bpd;
  const int s0 = (blockIdx.x % bpd) * 16;
  const __half* __restrict__ wd = g_wrec + (size_t)layer*131072 + (size_t)dir*65536;
  const int nbase = wp * 64;

  uint32_t bf[8][8][2];
  #pragma unroll
  for (int kc=0;kc<8;kc++)
    #pragma unroll
    for (int nt=0;nt<8;nt++){
      int n = nbase + nt*8 + (lane>>2);
      int k = kc*16 + (lane&3)*2;
      bf[kc][nt][0] = *(const uint32_t*)&wd[(size_t)n*128 + k];
      bf[kc][nt][1] = *(const uint32_t*)&wd[(size_t)n*128 + k + 8];
    }

  for (int i = tid; i < 16*136; i += 256) ((__half*)hsm)[i] = __ushort_as_half((unsigned short)0);

  const int sL = tid >> 4, jl = tid & 15;
  size_t posbase; int pstride;
  {
    int s = s0 + sL;
    if (scan_type == 0){ posbase = (size_t)s * 80; pstride = 1; }
    else { posbase = (size_t)(s/80)*4800 + (s%80); pstride = 80; }
  }
  float cst[8];
  #pragma unroll
  for (int u=0;u<8;u++) cst[u]=0.f;
  __syncthreads();

  for (int t=0; t<T; ++t){
    size_t pos = posbase + (size_t)(dir ? (T-1-t) : t) * pstride;
    const float* gp = g_gx + pos*1024 + dir*512;
    float gxr[32];
    #pragma unroll
    for (int g4=0; g4<4; ++g4)
      #pragma unroll
      for (int u=0;u<8;++u)
        gxr[g4*8+u] = gp[g4*128 + u*16 + jl];

    float acc[8][4];
    #pragma unroll
    for (int nt=0;nt<8;nt++)
      #pragma unroll
      for (int q=0;q<4;q++) acc[nt][q]=0.f;
    #pragma unroll
    for (int kc=0;kc<8;kc++){
      uint32_t a[4];
      ldsm4(a, &hsm[lane & 15][kc*16 + (lane>>4)*8]);
      #pragma unroll
      for (int nt=0;nt<8;nt++)
        mma16816(acc[nt], a, bf[kc][nt][0], bf[kc][nt][1]);
    }
    {
      int r = lane >> 2, cb = (lane & 3) * 2;
      #pragma unroll
      for (int nt=0;nt<8;nt++){
        int col = nbase + nt*8 + cb;
        float2 v0; v0.x = acc[nt][0]; v0.y = acc[nt][1];
        float2 v1; v1.x = acc[nt][2]; v1.y = acc[nt][3];
        *(float2*)&gsm[r][col]   = v0;
        *(float2*)&gsm[r+8][col] = v1;
      }
    }
    __syncthreads();
    #pragma unroll
    for (int u=0;u<8;u++){
      int j = u*16 + jl;
      float gi = gsm[sL][j]       + gxr[0*8+u];
      float gf = gsm[sL][128 + j] + gxr[1*8+u];
      float gg = gsm[sL][256 + j] + gxr[2*8+u];
      float go = gsm[sL][384 + j] + gxr[3*8+u];
      float c = sigm(gf)*cst[u] + sigm(gi)*tanh_(gg);
      cst[u] = c;
      float h = sigm(go)*tanh_(c);
      hsm[sL][j] = __float2half(h);
      yout[pos*256 + dir*128 + j] = __float2half(h);
    }
    __syncthreads();
  }
}

// ---------------- output head ----------------
__global__ __launch_bounds__(256) void k_conv_sig(
    int ysel, const float* __restrict__ cw, const float* __restrict__ cb){
  int tid = threadIdx.x, lane = tid & 31, wp = tid >> 5;
  const __half* Y = pick_x(ysel);
  float w[8];
  #pragma unroll
  for (int j=0;j<8;j++) w[j] = __ldg(&cw[lane*8 + j]);
  float b = __ldg(&cb[0]);
  #pragma unroll
  for (int it=0; it<4; ++it){
    int pos = blockIdx.x*32 + it*8 + wp;
    const __half* yp = Y + (size_t)pos*256 + lane*8;
    uint4 v = *(const uint4*)yp;
    const __half2* hv = (const __half2*)&v;
    float a = 0.f;
    #pragma unroll
    for (int j=0;j<4;j++){
      float2 f = __half22float2(hv[j]);
      a += f.x*w[2*j] + f.y*w[2*j+1];
    }
    #pragma unroll
    for (int d=16;d;d>>=1) a += __shfl_xor_sync(0xffffffffu, a, d);
    if (lane == 0) g_score[pos] = sigm(a + b);
  }
}

__global__ void k_upsample(float* __restrict__ out){
  int idx = blockIdx.x*blockDim.x + threadIdx.x;
  if (idx >= NB*480*640) return;
  int ox = idx % 640, oy = (idx/640) % 480, n = idx/(640*480);
  float sy = oy * (59.f/479.f);
  int iy = (int)sy; if (iy > 58) iy = 58;
  float ty = sy - (float)iy;
  float sx = ox * (79.f/639.f);
  int ix = (int)sx; if (ix > 78) ix = 78;
  float tx = sx - (float)ix;
  const float* sp = g_score + n*4800;
  float v00 = sp[iy*80+ix],     v01 = sp[iy*80+ix+1];
  float v10 = sp[(iy+1)*80+ix], v11 = sp[(iy+1)*80+ix+1];
  out[idx] = (v00*(1.f-ty)+v10*ty)*(1.f-tx) + (v01*(1.f-ty)+v11*ty)*tx;
}

// ---------------- launch ----------------
extern "C" void kernel_launch(void* const* d_in, const int* in_sizes, int n_in,
                              void* d_out, int out_size){
  const float* lf   = (const float*)d_in[0];
  const float* sc   = (const float*)d_in[1];
  const float* fc1w = (const float*)d_in[2];
  const float* fc1b = (const float*)d_in[3];
  const float* fcrw = (const float*)d_in[4];
  const float* fcrb = (const float*)d_in[5];
  const float* wih[4] = {(const float*)d_in[6], (const float*)d_in[9],
                         (const float*)d_in[12], (const float*)d_in[15]};
  const float* whh[4] = {(const float*)d_in[7], (const float*)d_in[10],
                         (const float*)d_in[13], (const float*)d_in[16]};
  const float* bb[4]  = {(const float*)d_in[8], (const float*)d_in[11],
                         (const float*)d_in[14], (const float*)d_in[17]};
  const float* cw = (const float*)d_in[18];
  const float* cb = (const float*)d_in[19];
  float* out = (float*)d_out;

  int bmoff[4] = {0, 512*1024, 768*1024, 1024*1024};
  int Is[4]    = {512, 256, 256, 256};

  // ordered so that launch index 5 (ncu -s 5 -c 1) is k_gemm_proj L0
  k_conv_wih<<<dim3(Is[0]/32, 32), dim3(32,8)>>>(wih[0], Is[0], bmoff[0]);   // 0
  k_cast_whh<<<512, 256>>>(whh[0], 0);                                       // 1
  k_scene_fc<<<96, 256>>>(sc, fc1w, fc1b, fcrw, fcrb);                       // 2
  k_scproj<<<4, 256>>>(bmoff[0], Is[0], 1, 0);                               // 3
  k_build_x1<<<dim3(150,16,8), dim3(32,8)>>>(lf);                            // 4
  k_gemm_proj<<<dim3(300,8), 256>>>(0, bmoff[0], bb[0], 0, 512, 0);          // 5 <- profiled
  k_scan<<<60, 256>>>(0, 1, 0, 80, 30);                                      // 6

  // layer 2: cols
  k_conv_wih<<<dim3(Is[1]/32, 32), dim3(32,8)>>>(wih[1], Is[1], bmoff[1]);
  k_cast_whh<<<512, 256>>>(whh[1], 131072);
  k_scproj<<<4, 256>>>(bmoff[1], Is[1], 0, 8192);
  k_gemm_proj<<<dim3(300,8), 256>>>(1, bmoff[1], bb[1], 8192, 256, 1);
  k_scan<<<80, 256>>>(1, 2, 1, 60, 40);

  // layer 3: rows
  k_conv_wih<<<dim3(Is[2]/32, 32), dim3(32,8)>>>(wih[2], Is[2], bmoff[2]);
  k_cast_whh<<<512, 256>>>(whh[2], 2*131072);
  k_scproj<<<4, 256>>>(bmoff[2], Is[2], 0, 16384);
  k_gemm_proj<<<dim3(300,8), 256>>>(2, bmoff[2], bb[2], 16384, 256, 0);
  k_scan<<<60, 256>>>(2, 1, 0, 80, 30);

  // layer 4: cols
  k_conv_wih<<<dim3(Is[3]/32, 32), dim3(32,8)>>>(wih[3], Is[3], bmoff[3]);
  k_cast_whh<<<512, 256>>>(whh[3], 3*131072);
  k_scproj<<<4, 256>>>(bmoff[3], Is[3], 0, 24576);
  k_gemm_proj<<<dim3(300,8), 256>>>(1, bmoff[3], bb[3], 24576, 256, 1);
  k_scan<<<80, 256>>>(3, 2, 1, 60, 40);

  k_conv_sig<<<1200, 256>>>(2, cw, cb);
  k_upsample<<<(NB*480*640 + 255)/256, 256>>>(out);
}